// round 11
// baseline (speedup 1.0000x reference)
#include <cuda_runtime.h>
#include <cuda_fp16.h>
#include <math.h>
#include <stdint.h>

// Problem constants
#define NTOK 1024
#define DIM  1024
#define HID  1024
#define NE   16
#define NK   4
#define NA   (NTOK*NK)
#define NOUT 10
#define NB   64
#define NM   16

// Scratch (device globals: allocation-free)
__device__ __align__(16) __half g_x16[(size_t)NTOK*DIM];   // 2 MB
__device__ __align__(16) __half g_h16[(size_t)NA*HID];     // 8 MB
__device__ __align__(16) float  g_o[(size_t)NA*DIM];       // 16 MB
__device__ __align__(16) __half g_w1h[(size_t)NE*DIM*HID]; // 32 MB
__device__ __align__(16) __half g_w2h[(size_t)NE*HID*DIM]; // 32 MB
__device__ int   g_tk_idx[NA];
__device__ float g_tk_gate[NA];
__device__ int   g_cnt[NE];
__device__ int   g_list[NE*NTOK];
__device__ float g_imp[NE];
__device__ float g_ld[NE];

__device__ __forceinline__ uint32_t smem_u32(const void* p) {
    uint32_t a;
    asm("{ .reg .u64 t; cvta.to.shared.u64 t, %1; cvt.u32.u64 %0, t; }" : "=r"(a) : "l"(p));
    return a;
}
__device__ __forceinline__ void ldsm4(uint32_t& r0, uint32_t& r1, uint32_t& r2, uint32_t& r3, uint32_t a) {
    asm volatile("ldmatrix.sync.aligned.m8n8.x4.shared.b16 {%0,%1,%2,%3}, [%4];"
                 : "=r"(r0), "=r"(r1), "=r"(r2), "=r"(r3) : "r"(a));
}
__device__ __forceinline__ void ldsm4t(uint32_t& r0, uint32_t& r1, uint32_t& r2, uint32_t& r3, uint32_t a) {
    asm volatile("ldmatrix.sync.aligned.m8n8.x4.trans.shared.b16 {%0,%1,%2,%3}, [%4];"
                 : "=r"(r0), "=r"(r1), "=r"(r2), "=r"(r3) : "r"(a));
}
__device__ __forceinline__ void mma16816(float* c, const uint32_t* a, uint32_t b0, uint32_t b1) {
    asm volatile("mma.sync.aligned.m16n8k16.row.col.f32.f16.f16.f32 "
                 "{%0,%1,%2,%3}, {%4,%5,%6,%7}, {%8,%9}, {%0,%1,%2,%3};"
                 : "+f"(c[0]), "+f"(c[1]), "+f"(c[2]), "+f"(c[3])
                 : "r"(a[0]), "r"(a[1]), "r"(a[2]), "r"(a[3]), "r"(b0), "r"(b1));
}
__device__ __forceinline__ void cp_async16(uint32_t dst, const void* src) {
    asm volatile("cp.async.cg.shared.global [%0], [%1], 16;" :: "r"(dst), "l"(src));
}
#define CP_COMMIT() asm volatile("cp.async.commit_group;" ::: "memory")
#define CP_WAIT(n)  asm volatile("cp.async.wait_group %0;" :: "n"(n) : "memory")

// Swizzles (conflict-free ldsm phases)
#define SWZA(row, cb)   ((row)*64  + ((cb) ^ ((((row)>>1)&3)<<4)))
#define SWZB(row, cb)   ((row)*256 + ((cb) ^ (((row)&7)<<4)))

// stage layout: A 8KB (128 rows x 64B) | B 8KB (32 k-rows x 256B), KC=32
#define S_A   0
#define S_B   (128*64)
#define STAGE_BYTES (128*64 + 32*256)     // 16KB
#define NSTAGE 4
#define SMEM_TOTAL  (NSTAGE*STAGE_BYTES)  // 64KB

__global__ void init_kernel() {
    if (threadIdx.x < NE) g_cnt[threadIdx.x] = 0;
}

// W fp32 -> fp16 (8 elems per thread)
__global__ void convert_w_kernel(const float* __restrict__ W, __half* __restrict__ Wh) {
    size_t i = ((size_t)blockIdx.x * 256 + threadIdx.x) * 8;
    float4 a = *(const float4*)(W + i);
    float4 b = *(const float4*)(W + i + 4);
    __half2 h[4];
    h[0] = __float22half2_rn(make_float2(a.x, a.y));
    h[1] = __float22half2_rn(make_float2(a.z, a.w));
    h[2] = __float22half2_rn(make_float2(b.x, b.y));
    h[3] = __float22half2_rn(make_float2(b.z, b.w));
    *(uint4*)(Wh + i) = *(uint4*)h;
}

// One block per token: logits, top-4, softmax, routing; also x -> fp16.
__global__ void gate_kernel(const float* __restrict__ x, const float* __restrict__ wg) {
    int n = blockIdx.x;
    int t = threadIdx.x;               // 256 threads
    float acc[16];
#pragma unroll
    for (int e = 0; e < 16; e++) acc[e] = 0.f;
    const float* xr = x + (size_t)n * DIM;
    __half* xo = g_x16 + (size_t)n * DIM;
    for (int d = t; d < DIM; d += 256) {
        float xv = xr[d];
        xo[d] = __float2half_rn(xv);
        const float4* w4 = (const float4*)(wg + (size_t)d * 16);
#pragma unroll
        for (int q = 0; q < 4; q++) {
            float4 w = w4[q];
            acc[q*4+0] = fmaf(xv, w.x, acc[q*4+0]);
            acc[q*4+1] = fmaf(xv, w.y, acc[q*4+1]);
            acc[q*4+2] = fmaf(xv, w.z, acc[q*4+2]);
            acc[q*4+3] = fmaf(xv, w.w, acc[q*4+3]);
        }
    }
#pragma unroll
    for (int e = 0; e < 16; e++)
        for (int off = 16; off; off >>= 1)
            acc[e] += __shfl_down_sync(0xffffffffu, acc[e], off);
    __shared__ float ws[8][16];
    int warp = t >> 5, lane = t & 31;
    if (lane == 0)
        for (int e = 0; e < 16; e++) ws[warp][e] = acc[e];
    __syncthreads();
    if (t == 0) {
        float l[16];
        for (int e = 0; e < 16; e++) {
            float s = 0.f;
            for (int w = 0; w < 8; w++) s += ws[w][e];
            l[e] = s;
        }
        int   idx[4];
        float val[4];
        for (int k = 0; k < 4; k++) {
            float best = -INFINITY; int bi = 0;
            for (int e = 0; e < 16; e++) if (l[e] > best) { best = l[e]; bi = e; }
            idx[k] = bi; val[k] = best; l[bi] = -INFINITY;
        }
        float mx = val[0], s = 0.f, ex[4];
        for (int k = 0; k < 4; k++) { ex[k] = expf(val[k] - mx); s += ex[k]; }
        float inv = 1.f / s;
        for (int k = 0; k < 4; k++) {
            float g = ex[k] * inv;
            int a = n * 4 + k;
            g_tk_idx[a]  = idx[k];
            g_tk_gate[a] = g;
            int slot = atomicAdd(&g_cnt[idx[k]], 1);
            g_list[idx[k] * NTOK + slot] = a;
        }
    }
}

// Aux loss: one block per expert, deterministic strided reduce.
__global__ void loss_part_kernel() {
    int e = blockIdx.x, t = threadIdx.x;
    float imp = 0.f, ld = 0.f;
    for (int a = t; a < NA; a += 256) {
        if (g_tk_idx[a] == e) { imp += g_tk_gate[a]; ld += 1.f; }
    }
    __shared__ float si[256], sl[256];
    si[t] = imp; sl[t] = ld; __syncthreads();
    for (int off = 128; off; off >>= 1) {
        if (t < off) { si[t] += si[t+off]; sl[t] += sl[t+off]; }
        __syncthreads();
    }
    if (t == 0) { g_imp[e] = si[0]; g_ld[e] = sl[0]; }
}

// Single fp16 expert GEMM, all-cp.async, 4-stage pipeline.
// CTA 128(M) x 128(N), KC=32, 8 warps = 2(m) x 4(n), warp tile 64x32.
__global__ void __launch_bounds__(256, 2)
expert_gemm_mma(const __half* __restrict__ Wh,
                const float* __restrict__ bias,
                int pass1) {
    int e   = blockIdx.z;
    int cnt = g_cnt[e];
    int m0  = blockIdx.y << 7;
    if (m0 >= cnt) return;
    int n0  = blockIdx.x << 7;

    extern __shared__ __align__(16) uint8_t smem[];
    __shared__ int rowid[128];

    const __half* We = Wh + (size_t)e * DIM * HID;

    int t = threadIdx.x, wid = t >> 5, lane = t & 31;

    if (t < 128) {
        int mi = m0 + t;
        rowid[t] = (mi < cnt) ? g_list[e * NTOK + mi] : -1;
    }
    __syncthreads();

    // A staging: row = t>>1, half = t&1 (16 fp16 = 32B; 2 x cp.async 16B)
    int arow = t >> 1, ahalf = t & 1;
    int aid_s = rowid[arow];
    int asrc = 0;
    if (aid_s >= 0) asrc = pass1 ? (aid_s >> 2) : aid_s;
    const __half* Arow = (pass1 ? g_x16 : g_h16) + (size_t)asrc * DIM + ahalf * 16;
    uint32_t aDst0 = (uint32_t)SWZA(arow, ahalf*32);
    uint32_t aDst1 = (uint32_t)SWZA(arow, ahalf*32 + 16);
    // B staging: krow = t>>3 (32 rows), 8 threads/row, 16 fp16 = 32B each
    int bkr = t >> 3, bseg = t & 7;
    const __half* Bptr = We + (size_t)bkr * HID + n0 + bseg * 16;
    uint32_t bDst0 = (uint32_t)SWZB(bkr, bseg*32);
    uint32_t bDst1 = (uint32_t)SWZB(bkr, bseg*32 + 16);

    uint32_t sbase = smem_u32(smem);
    int wm = wid & 1, wn = wid >> 1;

    float acc[4][4][4];
#pragma unroll
    for (int i = 0; i < 4; i++)
#pragma unroll
        for (int j = 0; j < 4; j++)
#pragma unroll
            for (int q = 0; q < 4; q++) acc[i][j][q] = 0.f;

#define ISSUE(c, stg)                                                          \
    do {                                                                       \
        uint32_t dS = sbase + (stg)*STAGE_BYTES;                               \
        int k0 = (c) * 32;                                                     \
        cp_async16(dS + S_A + aDst0, Arow + k0);                               \
        cp_async16(dS + S_A + aDst1, Arow + k0 + 8);                           \
        const __half* bp = Bptr + (size_t)k0 * HID;                            \
        cp_async16(dS + S_B + bDst0, bp);                                      \
        cp_async16(dS + S_B + bDst1, bp + 8);                                  \
        CP_COMMIT();                                                           \
    } while (0)

#define COMPUTE(stg)                                                           \
    do {                                                                       \
        uint32_t aB = sbase + (stg)*STAGE_BYTES + S_A;                         \
        uint32_t bB = sbase + (stg)*STAGE_BYTES + S_B;                         \
        _Pragma("unroll")                                                      \
        for (int ks = 0; ks < 2; ks++) {                                       \
            uint32_t ah[4][4];                                                 \
            _Pragma("unroll")                                                  \
            for (int i = 0; i < 4; i++) {                                      \
                int r = wm * 64 + i * 16 + (lane & 15);                        \
                int cb = ks*32 + ((lane >> 4) << 4);                           \
                ldsm4(ah[i][0], ah[i][1], ah[i][2], ah[i][3],                  \
                      aB + (uint32_t)SWZA(r, cb));                             \
            }                                                                  \
            uint32_t bh[4][2];                                                 \
            _Pragma("unroll")                                                  \
            for (int jp = 0; jp < 2; jp++) {                                   \
                int r = ks * 16 + (lane & 15);                                 \
                int cb = wn * 64 + jp * 32 + ((lane >> 4) << 4);               \
                uint32_t ad = (uint32_t)SWZB(r, cb);                           \
                uint32_t r0,r1,r2,r3;                                          \
                ldsm4t(r0, r1, r2, r3, bB + ad);                               \
                bh[jp*2][0]=r0; bh[jp*2][1]=r1; bh[jp*2+1][0]=r2; bh[jp*2+1][1]=r3; \
            }                                                                  \
            _Pragma("unroll")                                                  \
            for (int i = 0; i < 4; i++)                                        \
                _Pragma("unroll")                                              \
                for (int j = 0; j < 4; j++)                                    \
                    mma16816(acc[i][j], ah[i], bh[j][0], bh[j][1]);            \
        }                                                                      \
    } while (0)

#define NC (DIM/32)
    // Prologue: fill 3 stages
    ISSUE(0, 0);
    ISSUE(1, 1);
    ISSUE(2, 2);

#pragma unroll 1
    for (int c = 0; c < NC; c++) {
        int stg = c & 3;
        CP_WAIT(2);            // stage c complete (c+1, c+2 may be in flight)
        __syncthreads();       // all threads see stage c; all past compute(c-1)
        COMPUTE(stg);
        if (c + 3 < NC) {
            ISSUE(c + 3, (c + 3) & 3);
        } else {
            CP_COMMIT();       // keep group count in sync for CP_WAIT
        }
    }
#undef NC

    // Epilogue
    int colb = wn * 32 + (lane & 3) * 2;
    float2 bz[4];
#pragma unroll
    for (int j = 0; j < 4; j++)
        bz[j] = *(const float2*)(bias + e * HID + n0 + colb + j * 8);

#pragma unroll
    for (int i = 0; i < 4; i++) {
#pragma unroll
        for (int rh = 0; rh < 2; rh++) {
            int row = wm * 64 + i * 16 + rh * 8 + (lane >> 2);
            int aid = rowid[row];
            if (aid < 0) continue;
#pragma unroll
            for (int j = 0; j < 4; j++) {
                float ox = acc[i][j][rh*2+0] + bz[j].x;
                float oy = acc[i][j][rh*2+1] + bz[j].y;
                if (pass1) {
                    ox = fmaxf(ox, 0.f); oy = fmaxf(oy, 0.f);
                    __half2 h = __float22half2_rn(make_float2(ox, oy));
                    *(__half2*)(g_h16 + (size_t)aid * HID + n0 + colb + j * 8) = h;
                } else {
                    *(float2*)(g_o + (size_t)aid * DIM + n0 + colb + j * 8) = make_float2(ox, oy);
                }
            }
        }
    }
#undef ISSUE
#undef COMPUTE
}

__device__ float block_reduce_256(float v, volatile float* red) {
    int t = threadIdx.x;
    red[t] = v; __syncthreads();
    if (t < 128) red[t] += red[t + 128]; __syncthreads();
    if (t <  64) red[t] += red[t +  64]; __syncthreads();
    if (t <  32) {
        red[t] += red[t + 32]; __syncwarp();
        red[t] += red[t + 16]; __syncwarp();
        red[t] += red[t +  8]; __syncwarp();
        red[t] += red[t +  4]; __syncwarp();
        red[t] += red[t +  2]; __syncwarp();
        red[t] += red[t +  1]; __syncwarp();
    }
    __syncthreads();
    float r = red[0];
    __syncthreads();
    return r;
}

__global__ void finalize_kernel(const float* __restrict__ ln_w,
                                const float* __restrict__ ln_b,
                                const float* __restrict__ W_los,
                                const float* __restrict__ b_los,
                                float* __restrict__ d_out) {
    __shared__ float red[256];
    int b = blockIdx.x, t = threadIdx.x;
    float v[4];
#pragma unroll
    for (int i = 0; i < 4; i++) {
        int d = t + (i << 8);
        float acc = 0.f;
        for (int m = 0; m < NM; m++) {
            int n = (b << 4) + m;
#pragma unroll
            for (int k = 0; k < 4; k++) {
                int a = (n << 2) + k;
                acc = fmaf(g_tk_gate[a], g_o[(size_t)a * DIM + d], acc);
            }
        }
        v[i] = acc;
    }
    float s = 0.f, ss = 0.f;
#pragma unroll
    for (int i = 0; i < 4; i++) { s += v[i]; ss = fmaf(v[i], v[i], ss); }
    float sum   = block_reduce_256(s,  red);
    float sumsq = block_reduce_256(ss, red);
    float mu   = sum * (1.f / 1024.f);
    float var  = sumsq * (1.f / 1024.f) - mu * mu;
    float rstd = 1.f / sqrtf(var + 1e-5f);

    float sc[10];
#pragma unroll
    for (int o = 0; o < 10; o++) sc[o] = 0.f;
#pragma unroll
    for (int i = 0; i < 4; i++) {
        int d = t + (i << 8);
        float f = (v[i] - mu) * rstd * ln_w[d] + ln_b[d];
        const float* wl = W_los + (size_t)d * NOUT;
#pragma unroll
        for (int o = 0; o < 10; o++) sc[o] = fmaf(f, wl[o], sc[o]);
    }
    for (int o = 0; o < 10; o++) {
        float r = block_reduce_256(sc[o], red);
        if (t == 0) d_out[b * NOUT + o] = r + b_los[o];
    }
}

// MSE + aux-loss cv^2 combine.
__global__ void predloss_kernel(const float* __restrict__ true_y, float* __restrict__ d_out) {
    __shared__ float red[256];
    int t = threadIdx.x;
    float s = 0.f;
    for (int i = t; i < NB * NOUT; i += 256) {
        float dd = d_out[i] - true_y[i];
        s = fmaf(dd, dd, s);
    }
    float r = block_reduce_256(s, red);
    if (t == 0) {
        d_out[641] = r * (1.f / 640.f);
        float m1 = 0.f, m2 = 0.f;
        for (int e = 0; e < 16; e++) { m1 += g_imp[e]; m2 += g_ld[e]; }
        m1 *= (1.f/16.f); m2 *= (1.f/16.f);
        float v1 = 0.f, v2 = 0.f;
        for (int e = 0; e < 16; e++) {
            float a = g_imp[e] - m1, bb = g_ld[e] - m2;
            v1 += a * a; v2 += bb * bb;
        }
        v1 *= (1.f/15.f); v2 *= (1.f/15.f);
        float cv1 = v1 / (m1*m1 + 1e-10f);
        float cv2 = v2 / (m2*m2 + 1e-10f);
        d_out[640] = (cv1 + cv2) * 0.01f;
    }
}

extern "C" void kernel_launch(void* const* d_in, const int* in_sizes, int n_in,
                              void* d_out, int out_size) {
    const float* x      = (const float*)d_in[0];
    const float* wg     = (const float*)d_in[1];
    const float* W1     = (const float*)d_in[2];
    const float* b1     = (const float*)d_in[3];
    const float* W2     = (const float*)d_in[4];
    const float* b2     = (const float*)d_in[5];
    const float* ln_w   = (const float*)d_in[6];
    const float* ln_b   = (const float*)d_in[7];
    const float* W_los  = (const float*)d_in[8];
    const float* b_los  = (const float*)d_in[9];
    const float* true_y = (const float*)d_in[10];
    float* out = (float*)d_out;

    static cudaStream_t s2 = nullptr;
    static cudaEvent_t eFork = nullptr, eW1 = nullptr, eW2 = nullptr;
    if (!s2) {
        cudaFuncSetAttribute(expert_gemm_mma,
                             cudaFuncAttributeMaxDynamicSharedMemorySize, SMEM_TOTAL);
        cudaStreamCreateWithFlags(&s2, cudaStreamNonBlocking);
        cudaEventCreateWithFlags(&eFork, cudaEventDisableTiming);
        cudaEventCreateWithFlags(&eW1,   cudaEventDisableTiming);
        cudaEventCreateWithFlags(&eW2,   cudaEventDisableTiming);
    }

    __half *w1h = nullptr, *w2h = nullptr;
    cudaGetSymbolAddress((void**)&w1h, g_w1h);
    cudaGetSymbolAddress((void**)&w2h, g_w2h);

    // Fork: weight conversion runs on s2, overlapped with gate/loss and GEMM1.
    cudaEventRecord(eFork, 0);
    cudaStreamWaitEvent(s2, eFork, 0);
    convert_w_kernel<<<8192, 256, 0, s2>>>(W1, w1h);
    cudaEventRecord(eW1, s2);
    convert_w_kernel<<<8192, 256, 0, s2>>>(W2, w2h);
    cudaEventRecord(eW2, s2);

    // Main stream: routing work (independent of W conversion)
    init_kernel<<<1, 32>>>();
    gate_kernel<<<NTOK, 256>>>(x, wg);
    loss_part_kernel<<<16, 256>>>();

    cudaStreamWaitEvent(0, eW1, 0);     // need w1h
    expert_gemm_mma<<<dim3(8, 8, 16), 256, SMEM_TOTAL>>>(w1h, b1, 1);
    cudaStreamWaitEvent(0, eW2, 0);     // need w2h (join s2)
    expert_gemm_mma<<<dim3(8, 8, 16), 256, SMEM_TOTAL>>>(w2h, b2, 0);
    finalize_kernel<<<64, 256>>>(ln_w, ln_b, W_los, b_los, out);
    predloss_kernel<<<1, 256>>>(true_y, out);
}

// round 12
// speedup vs baseline: 1.0796x; 1.0796x over previous
#include <cuda_runtime.h>
#include <cuda_fp16.h>
#include <math.h>
#include <stdint.h>

// Problem constants
#define NTOK 1024
#define DIM  1024
#define HID  1024
#define NE   16
#define NK   4
#define NA   (NTOK*NK)
#define NOUT 10
#define NB   64
#define NM   16

// Scratch (device globals: allocation-free)
__device__ __align__(16) __half g_x16[(size_t)NTOK*DIM];   // 2 MB
__device__ __align__(16) __half g_h16[(size_t)NA*HID];     // 8 MB
__device__ __align__(16) __half g_o16[(size_t)NA*DIM];     // 8 MB
__device__ __align__(16) __half g_w1h[(size_t)NE*DIM*HID]; // 32 MB
__device__ __align__(16) __half g_w2h[(size_t)NE*HID*DIM]; // 32 MB
__device__ int   g_tk_idx[NA];
__device__ float g_tk_gate[NA];
__device__ int   g_cnt[NE];
__device__ int   g_list[NE*NTOK];
__device__ float g_imp[NE];
__device__ float g_ld[NE];

__device__ __forceinline__ uint32_t smem_u32(const void* p) {
    uint32_t a;
    asm("{ .reg .u64 t; cvta.to.shared.u64 t, %1; cvt.u32.u64 %0, t; }" : "=r"(a) : "l"(p));
    return a;
}
__device__ __forceinline__ void ldsm4(uint32_t& r0, uint32_t& r1, uint32_t& r2, uint32_t& r3, uint32_t a) {
    asm volatile("ldmatrix.sync.aligned.m8n8.x4.shared.b16 {%0,%1,%2,%3}, [%4];"
                 : "=r"(r0), "=r"(r1), "=r"(r2), "=r"(r3) : "r"(a));
}
__device__ __forceinline__ void ldsm4t(uint32_t& r0, uint32_t& r1, uint32_t& r2, uint32_t& r3, uint32_t a) {
    asm volatile("ldmatrix.sync.aligned.m8n8.x4.trans.shared.b16 {%0,%1,%2,%3}, [%4];"
                 : "=r"(r0), "=r"(r1), "=r"(r2), "=r"(r3) : "r"(a));
}
__device__ __forceinline__ void mma16816(float* c, const uint32_t* a, uint32_t b0, uint32_t b1) {
    asm volatile("mma.sync.aligned.m16n8k16.row.col.f32.f16.f16.f32 "
                 "{%0,%1,%2,%3}, {%4,%5,%6,%7}, {%8,%9}, {%0,%1,%2,%3};"
                 : "+f"(c[0]), "+f"(c[1]), "+f"(c[2]), "+f"(c[3])
                 : "r"(a[0]), "r"(a[1]), "r"(a[2]), "r"(a[3]), "r"(b0), "r"(b1));
}
__device__ __forceinline__ void cp_async16(uint32_t dst, const void* src) {
    asm volatile("cp.async.cg.shared.global [%0], [%1], 16;" :: "r"(dst), "l"(src));
}
#define CP_COMMIT() asm volatile("cp.async.commit_group;" ::: "memory")
#define CP_WAIT(n)  asm volatile("cp.async.wait_group %0;" :: "n"(n) : "memory")

// Swizzles (conflict-free ldsm phases)
#define SWZA(row, cb)   ((row)*64  + ((cb) ^ ((((row)>>1)&3)<<4)))
#define SWZB(row, cb)   ((row)*256 + ((cb) ^ (((row)&7)<<4)))

// stage layout: A 8KB (128 rows x 64B) | B 8KB (32 k-rows x 256B), KC=32
#define S_A   0
#define S_B   (128*64)
#define STAGE_BYTES (128*64 + 32*256)     // 16KB
#define NSTAGE 4
#define SMEM_TOTAL  (NSTAGE*STAGE_BYTES)  // 64KB

// W fp32 -> fp16 (8 elems per thread)
__global__ void convert_w_kernel(const float* __restrict__ W, __half* __restrict__ Wh) {
    size_t i = ((size_t)blockIdx.x * 256 + threadIdx.x) * 8;
    float4 a = *(const float4*)(W + i);
    float4 b = *(const float4*)(W + i + 4);
    __half2 h[4];
    h[0] = __float22half2_rn(make_float2(a.x, a.y));
    h[1] = __float22half2_rn(make_float2(a.z, a.w));
    h[2] = __float22half2_rn(make_float2(b.x, b.y));
    h[3] = __float22half2_rn(make_float2(b.z, b.w));
    *(uint4*)(Wh + i) = *(uint4*)h;
}

// Warp-per-token gate: logits, top-4, softmax, routing; also x -> fp16.
// 128 blocks x 256 threads = 1024 warps = 1024 tokens.
__global__ void gate_kernel(const float* __restrict__ x, const float* __restrict__ wg) {
    int w = threadIdx.x >> 5, lane = threadIdx.x & 31;
    int n = blockIdx.x * 8 + w;
    const float* xr = x + (size_t)n * DIM;
    __half* xo = g_x16 + (size_t)n * DIM;

    float acc[16];
#pragma unroll
    for (int e = 0; e < 16; e++) acc[e] = 0.f;

#pragma unroll
    for (int i = 0; i < 8; i++) {
        int d0 = i * 128 + lane * 4;
        float4 xv = *(const float4*)(xr + d0);
        __half2 h0 = __float22half2_rn(make_float2(xv.x, xv.y));
        __half2 h1 = __float22half2_rn(make_float2(xv.z, xv.w));
        uint2 hp; hp.x = *(uint32_t*)&h0; hp.y = *(uint32_t*)&h1;
        *(uint2*)(xo + d0) = hp;
        float xs[4] = {xv.x, xv.y, xv.z, xv.w};
#pragma unroll
        for (int j = 0; j < 4; j++) {
            const float4* wr = (const float4*)(wg + (size_t)(d0 + j) * 16);
#pragma unroll
            for (int q = 0; q < 4; q++) {
                float4 ww = wr[q];
                acc[q*4+0] = fmaf(xs[j], ww.x, acc[q*4+0]);
                acc[q*4+1] = fmaf(xs[j], ww.y, acc[q*4+1]);
                acc[q*4+2] = fmaf(xs[j], ww.z, acc[q*4+2]);
                acc[q*4+3] = fmaf(xs[j], ww.w, acc[q*4+3]);
            }
        }
    }
#pragma unroll
    for (int e = 0; e < 16; e++)
#pragma unroll
        for (int off = 16; off; off >>= 1)
            acc[e] += __shfl_xor_sync(0xffffffffu, acc[e], off);

    if (lane == 0) {
        int   idx[4];
        float val[4];
#pragma unroll
        for (int k = 0; k < 4; k++) {       // strict > : lowest index wins ties
            float best = -INFINITY; int bi = 0;
            for (int e = 0; e < 16; e++) if (acc[e] > best) { best = acc[e]; bi = e; }
            idx[k] = bi; val[k] = best; acc[bi] = -INFINITY;
        }
        float mx = val[0], s = 0.f, ex[4];
#pragma unroll
        for (int k = 0; k < 4; k++) { ex[k] = expf(val[k] - mx); s += ex[k]; }
        float inv = 1.f / s;
#pragma unroll
        for (int k = 0; k < 4; k++) {
            float g = ex[k] * inv;
            int a = n * 4 + k;
            g_tk_idx[a]  = idx[k];
            g_tk_gate[a] = g;
            int slot = atomicAdd(&g_cnt[idx[k]], 1);
            g_list[idx[k] * NTOK + slot] = a;   // list order irrelevant downstream
        }
    }
}

// Aux loss: one block per expert, deterministic strided reduce.
__global__ void loss_part_kernel() {
    int e = blockIdx.x, t = threadIdx.x;
    float imp = 0.f, ld = 0.f;
    for (int a = t; a < NA; a += 256) {
        if (g_tk_idx[a] == e) { imp += g_tk_gate[a]; ld += 1.f; }
    }
    __shared__ float si[256], sl[256];
    si[t] = imp; sl[t] = ld; __syncthreads();
    for (int off = 128; off; off >>= 1) {
        if (t < off) { si[t] += si[t+off]; sl[t] += sl[t+off]; }
        __syncthreads();
    }
    if (t == 0) { g_imp[e] = si[0]; g_ld[e] = sl[0]; }
}

// Single fp16 expert GEMM, all-cp.async, 4-stage pipeline.
// CTA 128(M) x 128(N), KC=32, 8 warps = 2(m) x 4(n), warp tile 64x32.
__global__ void __launch_bounds__(256, 2)
expert_gemm_mma(const __half* __restrict__ Wh,
                const float* __restrict__ bias,
                int pass1) {
    int e   = blockIdx.z;
    int cnt = g_cnt[e];
    int m0  = blockIdx.y << 7;
    if (m0 >= cnt) return;
    int n0  = blockIdx.x << 7;

    extern __shared__ __align__(16) uint8_t smem[];
    __shared__ int rowid[128];

    const __half* We = Wh + (size_t)e * DIM * HID;

    int t = threadIdx.x, wid = t >> 5, lane = t & 31;

    if (t < 128) {
        int mi = m0 + t;
        rowid[t] = (mi < cnt) ? g_list[e * NTOK + mi] : -1;
    }
    __syncthreads();

    // A staging: row = t>>1, half = t&1 (16 fp16 = 32B; 2 x cp.async 16B)
    int arow = t >> 1, ahalf = t & 1;
    int aid_s = rowid[arow];
    int asrc = 0;
    if (aid_s >= 0) asrc = pass1 ? (aid_s >> 2) : aid_s;
    const __half* Arow = (pass1 ? g_x16 : g_h16) + (size_t)asrc * DIM + ahalf * 16;
    uint32_t aDst0 = (uint32_t)SWZA(arow, ahalf*32);
    uint32_t aDst1 = (uint32_t)SWZA(arow, ahalf*32 + 16);
    // B staging: krow = t>>3 (32 rows), 8 threads/row, 16 fp16 = 32B each
    int bkr = t >> 3, bseg = t & 7;
    const __half* Bptr = We + (size_t)bkr * HID + n0 + bseg * 16;
    uint32_t bDst0 = (uint32_t)SWZB(bkr, bseg*32);
    uint32_t bDst1 = (uint32_t)SWZB(bkr, bseg*32 + 16);

    uint32_t sbase = smem_u32(smem);
    int wm = wid & 1, wn = wid >> 1;

    float acc[4][4][4];
#pragma unroll
    for (int i = 0; i < 4; i++)
#pragma unroll
        for (int j = 0; j < 4; j++)
#pragma unroll
            for (int q = 0; q < 4; q++) acc[i][j][q] = 0.f;

#define ISSUE(c, stg)                                                          \
    do {                                                                       \
        uint32_t dS = sbase + (stg)*STAGE_BYTES;                               \
        int k0 = (c) * 32;                                                     \
        cp_async16(dS + S_A + aDst0, Arow + k0);                               \
        cp_async16(dS + S_A + aDst1, Arow + k0 + 8);                           \
        const __half* bp = Bptr + (size_t)k0 * HID;                            \
        cp_async16(dS + S_B + bDst0, bp);                                      \
        cp_async16(dS + S_B + bDst1, bp + 8);                                  \
        CP_COMMIT();                                                           \
    } while (0)

#define COMPUTE(stg)                                                           \
    do {                                                                       \
        uint32_t aB = sbase + (stg)*STAGE_BYTES + S_A;                         \
        uint32_t bB = sbase + (stg)*STAGE_BYTES + S_B;                         \
        _Pragma("unroll")                                                      \
        for (int ks = 0; ks < 2; ks++) {                                       \
            uint32_t ah[4][4];                                                 \
            _Pragma("unroll")                                                  \
            for (int i = 0; i < 4; i++) {                                      \
                int r = wm * 64 + i * 16 + (lane & 15);                        \
                int cb = ks*32 + ((lane >> 4) << 4);                           \
                ldsm4(ah[i][0], ah[i][1], ah[i][2], ah[i][3],                  \
                      aB + (uint32_t)SWZA(r, cb));                             \
            }                                                                  \
            uint32_t bh[4][2];                                                 \
            _Pragma("unroll")                                                  \
            for (int jp = 0; jp < 2; jp++) {                                   \
                int r = ks * 16 + (lane & 15);                                 \
                int cb = wn * 64 + jp * 32 + ((lane >> 4) << 4);               \
                uint32_t ad = (uint32_t)SWZB(r, cb);                           \
                uint32_t r0,r1,r2,r3;                                          \
                ldsm4t(r0, r1, r2, r3, bB + ad);                               \
                bh[jp*2][0]=r0; bh[jp*2][1]=r1; bh[jp*2+1][0]=r2; bh[jp*2+1][1]=r3; \
            }                                                                  \
            _Pragma("unroll")                                                  \
            for (int i = 0; i < 4; i++)                                        \
                _Pragma("unroll")                                              \
                for (int j = 0; j < 4; j++)                                    \
                    mma16816(acc[i][j], ah[i], bh[j][0], bh[j][1]);            \
        }                                                                      \
    } while (0)

#define NC (DIM/32)
    // Prologue: fill 3 stages
    ISSUE(0, 0);
    ISSUE(1, 1);
    ISSUE(2, 2);

#pragma unroll 1
    for (int c = 0; c < NC; c++) {
        int stg = c & 3;
        CP_WAIT(2);            // stage c complete (c+1, c+2 may be in flight)
        __syncthreads();       // all threads see stage c; all past compute(c-1)
        COMPUTE(stg);
        if (c + 3 < NC) {
            ISSUE(c + 3, (c + 3) & 3);
        } else {
            CP_COMMIT();       // keep group count in sync for CP_WAIT
        }
    }
#undef NC

    // Epilogue (fp16 outputs for both passes)
    int colb = wn * 32 + (lane & 3) * 2;
    float2 bz[4];
#pragma unroll
    for (int j = 0; j < 4; j++)
        bz[j] = *(const float2*)(bias + e * HID + n0 + colb + j * 8);

#pragma unroll
    for (int i = 0; i < 4; i++) {
#pragma unroll
        for (int rh = 0; rh < 2; rh++) {
            int row = wm * 64 + i * 16 + rh * 8 + (lane >> 2);
            int aid = rowid[row];
            if (aid < 0) continue;
#pragma unroll
            for (int j = 0; j < 4; j++) {
                float ox = acc[i][j][rh*2+0] + bz[j].x;
                float oy = acc[i][j][rh*2+1] + bz[j].y;
                if (pass1) {
                    ox = fmaxf(ox, 0.f); oy = fmaxf(oy, 0.f);
                    __half2 h = __float22half2_rn(make_float2(ox, oy));
                    *(__half2*)(g_h16 + (size_t)aid * HID + n0 + colb + j * 8) = h;
                } else {
                    __half2 h = __float22half2_rn(make_float2(ox, oy));
                    *(__half2*)(g_o16 + (size_t)aid * DIM + n0 + colb + j * 8) = h;
                }
            }
        }
    }
#undef ISSUE
#undef COMPUTE
}

__device__ float block_reduce_256(float v, volatile float* red) {
    int t = threadIdx.x;
    red[t] = v; __syncthreads();
    if (t < 128) red[t] += red[t + 128]; __syncthreads();
    if (t <  64) red[t] += red[t +  64]; __syncthreads();
    if (t <  32) {
        red[t] += red[t + 32]; __syncwarp();
        red[t] += red[t + 16]; __syncwarp();
        red[t] += red[t +  8]; __syncwarp();
        red[t] += red[t +  4]; __syncwarp();
        red[t] += red[t +  2]; __syncwarp();
        red[t] += red[t +  1]; __syncwarp();
    }
    __syncthreads();
    float r = red[0];
    __syncthreads();
    return r;
}

// Combine (fp16 g_o16), layernorm, head, MSE partials + aux loss.
// d_out[641] must be zeroed before this kernel (memset node).
__global__ void finalize_kernel(const float* __restrict__ ln_w,
                                const float* __restrict__ ln_b,
                                const float* __restrict__ W_los,
                                const float* __restrict__ b_los,
                                const float* __restrict__ true_y,
                                float* __restrict__ d_out) {
    __shared__ float red[256];
    int b = blockIdx.x, t = threadIdx.x;
    float v[2][2];
#pragma unroll
    for (int i = 0; i < 2; i++) {
        int d0 = i * 512 + t * 2;
        float a0 = 0.f, a1 = 0.f;
        for (int m = 0; m < NM; m++) {
            int n = (b << 4) + m;
#pragma unroll
            for (int k = 0; k < 4; k++) {
                int a = (n << 2) + k;
                __half2 h = *(const __half2*)(g_o16 + (size_t)a * DIM + d0);
                float2 f = __half22float2(h);
                float g = g_tk_gate[a];
                a0 = fmaf(g, f.x, a0);
                a1 = fmaf(g, f.y, a1);
            }
        }
        v[i][0] = a0; v[i][1] = a1;
    }
    float s = 0.f, ss = 0.f;
#pragma unroll
    for (int i = 0; i < 2; i++)
#pragma unroll
        for (int p = 0; p < 2; p++) { s += v[i][p]; ss = fmaf(v[i][p], v[i][p], ss); }
    float sum   = block_reduce_256(s,  red);
    float sumsq = block_reduce_256(ss, red);
    float mu   = sum * (1.f / 1024.f);
    float var  = sumsq * (1.f / 1024.f) - mu * mu;
    float rstd = 1.f / sqrtf(var + 1e-5f);

    float sc[10];
#pragma unroll
    for (int o = 0; o < 10; o++) sc[o] = 0.f;
#pragma unroll
    for (int i = 0; i < 2; i++)
#pragma unroll
        for (int p = 0; p < 2; p++) {
            int d = i * 512 + t * 2 + p;
            float f = (v[i][p] - mu) * rstd * ln_w[d] + ln_b[d];
            const float* wl = W_los + (size_t)d * NOUT;
#pragma unroll
            for (int o = 0; o < 10; o++) sc[o] = fmaf(f, wl[o], sc[o]);
        }
    float mse = 0.f;
    for (int o = 0; o < 10; o++) {
        float r = block_reduce_256(sc[o], red);
        if (t == 0) {
            float sval = r + b_los[o];
            d_out[b * NOUT + o] = sval;
            float dd = sval - true_y[b * NOUT + o];
            mse = fmaf(dd, dd, mse);
        }
    }
    if (t == 0) {
        atomicAdd(&d_out[641], mse * (1.f / 640.f));
        if (b == 0) {
            float m1 = 0.f, m2 = 0.f;
            for (int e = 0; e < 16; e++) { m1 += g_imp[e]; m2 += g_ld[e]; }
            m1 *= (1.f/16.f); m2 *= (1.f/16.f);
            float v1 = 0.f, v2 = 0.f;
            for (int e = 0; e < 16; e++) {
                float a = g_imp[e] - m1, bb = g_ld[e] - m2;
                v1 += a * a; v2 += bb * bb;
            }
            v1 *= (1.f/15.f); v2 *= (1.f/15.f);
            float cv1 = v1 / (m1*m1 + 1e-10f);
            float cv2 = v2 / (m2*m2 + 1e-10f);
            d_out[640] = (cv1 + cv2) * 0.01f;
        }
    }
}

extern "C" void kernel_launch(void* const* d_in, const int* in_sizes, int n_in,
                              void* d_out, int out_size) {
    const float* x      = (const float*)d_in[0];
    const float* wg     = (const float*)d_in[1];
    const float* W1     = (const float*)d_in[2];
    const float* b1     = (const float*)d_in[3];
    const float* W2     = (const float*)d_in[4];
    const float* b2     = (const float*)d_in[5];
    const float* ln_w   = (const float*)d_in[6];
    const float* ln_b   = (const float*)d_in[7];
    const float* W_los  = (const float*)d_in[8];
    const float* b_los  = (const float*)d_in[9];
    const float* true_y = (const float*)d_in[10];
    float* out = (float*)d_out;

    static int inited = 0;
    static void* cnt_addr = nullptr;
    if (!inited) {
        cudaFuncSetAttribute(expert_gemm_mma,
                             cudaFuncAttributeMaxDynamicSharedMemorySize, SMEM_TOTAL);
        cudaGetSymbolAddress(&cnt_addr, g_cnt);
        inited = 1;
    }

    __half *w1h = nullptr, *w2h = nullptr;
    cudaGetSymbolAddress((void**)&w1h, g_w1h);
    cudaGetSymbolAddress((void**)&w2h, g_w2h);

    cudaMemsetAsync(cnt_addr, 0, NE * sizeof(int), 0);
    cudaMemsetAsync(out + 641, 0, sizeof(float), 0);
    gate_kernel<<<128, 256>>>(x, wg);
    loss_part_kernel<<<16, 256>>>();
    convert_w_kernel<<<8192, 256>>>(W1, w1h);
    convert_w_kernel<<<8192, 256>>>(W2, w2h);
    expert_gemm_mma<<<dim3(8, 8, 16), 256, SMEM_TOTAL>>>(w1h, b1, 1);
    expert_gemm_mma<<<dim3(8, 8, 16), 256, SMEM_TOTAL>>>(w2h, b2, 0);
    finalize_kernel<<<64, 256>>>(ln_w, ln_b, W_los, b_los, true_y, out);
}

// round 13
// speedup vs baseline: 1.1297x; 1.0464x over previous
#include <cuda_runtime.h>
#include <cuda_fp16.h>
#include <math.h>
#include <stdint.h>

// Problem constants
#define NTOK 1024
#define DIM  1024
#define HID  1024
#define NE   16
#define NK   4
#define NA   (NTOK*NK)
#define NOUT 10
#define NB   64
#define NM   16

// Scratch (device globals: allocation-free)
__device__ __align__(16) __half g_x16[(size_t)NTOK*DIM];   // 2 MB
__device__ __align__(16) __half g_h16[(size_t)NA*HID];     // 8 MB
__device__ __align__(16) __half g_o16[(size_t)NA*DIM];     // 8 MB
__device__ __align__(16) __half g_w1h[(size_t)NE*DIM*HID]; // 32 MB
__device__ __align__(16) __half g_w2h[(size_t)NE*HID*DIM]; // 32 MB
__device__ int   g_tk_idx[NA];
__device__ float g_tk_gate[NA];
__device__ int   g_cnt[NE];
__device__ int   g_list[NE*NTOK];
__device__ float g_impld[2*NE];   // [0:16) importance, [16:32) load

__device__ __forceinline__ uint32_t smem_u32(const void* p) {
    uint32_t a;
    asm("{ .reg .u64 t; cvta.to.shared.u64 t, %1; cvt.u32.u64 %0, t; }" : "=r"(a) : "l"(p));
    return a;
}
__device__ __forceinline__ void ldsm4(uint32_t& r0, uint32_t& r1, uint32_t& r2, uint32_t& r3, uint32_t a) {
    asm volatile("ldmatrix.sync.aligned.m8n8.x4.shared.b16 {%0,%1,%2,%3}, [%4];"
                 : "=r"(r0), "=r"(r1), "=r"(r2), "=r"(r3) : "r"(a));
}
__device__ __forceinline__ void ldsm4t(uint32_t& r0, uint32_t& r1, uint32_t& r2, uint32_t& r3, uint32_t a) {
    asm volatile("ldmatrix.sync.aligned.m8n8.x4.trans.shared.b16 {%0,%1,%2,%3}, [%4];"
                 : "=r"(r0), "=r"(r1), "=r"(r2), "=r"(r3) : "r"(a));
}
__device__ __forceinline__ void mma16816(float* c, const uint32_t* a, uint32_t b0, uint32_t b1) {
    asm volatile("mma.sync.aligned.m16n8k16.row.col.f32.f16.f16.f32 "
                 "{%0,%1,%2,%3}, {%4,%5,%6,%7}, {%8,%9}, {%0,%1,%2,%3};"
                 : "+f"(c[0]), "+f"(c[1]), "+f"(c[2]), "+f"(c[3])
                 : "r"(a[0]), "r"(a[1]), "r"(a[2]), "r"(a[3]), "r"(b0), "r"(b1));
}
__device__ __forceinline__ void cp_async16(uint32_t dst, const void* src) {
    asm volatile("cp.async.cg.shared.global [%0], [%1], 16;" :: "r"(dst), "l"(src));
}
#define CP_COMMIT() asm volatile("cp.async.commit_group;" ::: "memory")
#define CP_WAIT(n)  asm volatile("cp.async.wait_group %0;" :: "n"(n) : "memory")

// Swizzles (conflict-free ldsm phases)
#define SWZA(row, cb)   ((row)*64  + ((cb) ^ ((((row)>>1)&3)<<4)))
#define SWZB(row, cb)   ((row)*256 + ((cb) ^ (((row)&7)<<4)))

// stage layout: A 8KB (128 rows x 64B) | B 8KB (32 k-rows x 256B), KC=32
#define S_A   0
#define S_B   (128*64)
#define STAGE_BYTES (128*64 + 32*256)     // 16KB
#define NSTAGE 4
#define SMEM_TOTAL  (NSTAGE*STAGE_BYTES)  // 64KB

// Both W1 and W2 fp32 -> fp16 in ONE launch (grid 16384; upper half = W2)
__global__ void convert_w_kernel(const float* __restrict__ W1, __half* __restrict__ W1h,
                                 const float* __restrict__ W2, __half* __restrict__ W2h) {
    int blk = blockIdx.x;
    const float* W  = (blk < 8192) ? W1  : W2;
    __half*      Wh = (blk < 8192) ? W1h : W2h;
    if (blk >= 8192) blk -= 8192;
    size_t i = ((size_t)blk * 256 + threadIdx.x) * 8;
    float4 a = *(const float4*)(W + i);
    float4 b = *(const float4*)(W + i + 4);
    __half2 h[4];
    h[0] = __float22half2_rn(make_float2(a.x, a.y));
    h[1] = __float22half2_rn(make_float2(a.z, a.w));
    h[2] = __float22half2_rn(make_float2(b.x, b.y));
    h[3] = __float22half2_rn(make_float2(b.z, b.w));
    *(uint4*)(Wh + i) = *(uint4*)h;
}

// Warp-per-token gate: logits, top-4, softmax, routing, aux-loss sums; x -> fp16.
// 128 blocks x 256 threads = 1024 warps = 1024 tokens.
__global__ void gate_kernel(const float* __restrict__ x, const float* __restrict__ wg) {
    int w = threadIdx.x >> 5, lane = threadIdx.x & 31;
    int n = blockIdx.x * 8 + w;
    const float* xr = x + (size_t)n * DIM;
    __half* xo = g_x16 + (size_t)n * DIM;

    float acc[16];
#pragma unroll
    for (int e = 0; e < 16; e++) acc[e] = 0.f;

#pragma unroll
    for (int i = 0; i < 8; i++) {
        int d0 = i * 128 + lane * 4;
        float4 xv = *(const float4*)(xr + d0);
        __half2 h0 = __float22half2_rn(make_float2(xv.x, xv.y));
        __half2 h1 = __float22half2_rn(make_float2(xv.z, xv.w));
        uint2 hp; hp.x = *(uint32_t*)&h0; hp.y = *(uint32_t*)&h1;
        *(uint2*)(xo + d0) = hp;
        float xs[4] = {xv.x, xv.y, xv.z, xv.w};
#pragma unroll
        for (int j = 0; j < 4; j++) {
            const float4* wr = (const float4*)(wg + (size_t)(d0 + j) * 16);
#pragma unroll
            for (int q = 0; q < 4; q++) {
                float4 ww = wr[q];
                acc[q*4+0] = fmaf(xs[j], ww.x, acc[q*4+0]);
                acc[q*4+1] = fmaf(xs[j], ww.y, acc[q*4+1]);
                acc[q*4+2] = fmaf(xs[j], ww.z, acc[q*4+2]);
                acc[q*4+3] = fmaf(xs[j], ww.w, acc[q*4+3]);
            }
        }
    }
#pragma unroll
    for (int e = 0; e < 16; e++)
#pragma unroll
        for (int off = 16; off; off >>= 1)
            acc[e] += __shfl_xor_sync(0xffffffffu, acc[e], off);

    if (lane == 0) {
        int   idx[4];
        float val[4];
#pragma unroll
        for (int k = 0; k < 4; k++) {       // strict > : lowest index wins ties
            float best = -INFINITY; int bi = 0;
            for (int e = 0; e < 16; e++) if (acc[e] > best) { best = acc[e]; bi = e; }
            idx[k] = bi; val[k] = best; acc[bi] = -INFINITY;
        }
        float mx = val[0], s = 0.f, ex[4];
#pragma unroll
        for (int k = 0; k < 4; k++) { ex[k] = expf(val[k] - mx); s += ex[k]; }
        float inv = 1.f / s;
#pragma unroll
        for (int k = 0; k < 4; k++) {
            float g = ex[k] * inv;
            int a = n * 4 + k;
            g_tk_idx[a]  = idx[k];
            g_tk_gate[a] = g;
            int slot = atomicAdd(&g_cnt[idx[k]], 1);
            g_list[idx[k] * NTOK + slot] = a;   // list order irrelevant downstream
            atomicAdd(&g_impld[idx[k]], g);       // importance
            atomicAdd(&g_impld[16 + idx[k]], 1.f);// load
        }
    }
}

// Single fp16 expert GEMM, all-cp.async, 4-stage pipeline.
// CTA 128(M) x 128(N), KC=32, 8 warps = 2(m) x 4(n), warp tile 64x32.
__global__ void __launch_bounds__(256, 2)
expert_gemm_mma(const __half* __restrict__ Wh,
                const float* __restrict__ bias,
                int pass1) {
    int e   = blockIdx.z;
    int cnt = g_cnt[e];
    int m0  = blockIdx.y << 7;
    if (m0 >= cnt) return;
    int n0  = blockIdx.x << 7;

    extern __shared__ __align__(16) uint8_t smem[];
    __shared__ int rowid[128];

    const __half* We = Wh + (size_t)e * DIM * HID;

    int t = threadIdx.x, wid = t >> 5, lane = t & 31;

    if (t < 128) {
        int mi = m0 + t;
        rowid[t] = (mi < cnt) ? g_list[e * NTOK + mi] : -1;
    }
    __syncthreads();

    // A staging: row = t>>1, half = t&1 (16 fp16 = 32B; 2 x cp.async 16B)
    int arow = t >> 1, ahalf = t & 1;
    int aid_s = rowid[arow];
    int asrc = 0;
    if (aid_s >= 0) asrc = pass1 ? (aid_s >> 2) : aid_s;
    const __half* Arow = (pass1 ? g_x16 : g_h16) + (size_t)asrc * DIM + ahalf * 16;
    uint32_t aDst0 = (uint32_t)SWZA(arow, ahalf*32);
    uint32_t aDst1 = (uint32_t)SWZA(arow, ahalf*32 + 16);
    // B staging: krow = t>>3 (32 rows), 8 threads/row, 16 fp16 = 32B each
    int bkr = t >> 3, bseg = t & 7;
    const __half* Bptr = We + (size_t)bkr * HID + n0 + bseg * 16;
    uint32_t bDst0 = (uint32_t)SWZB(bkr, bseg*32);
    uint32_t bDst1 = (uint32_t)SWZB(bkr, bseg*32 + 16);

    uint32_t sbase = smem_u32(smem);
    int wm = wid & 1, wn = wid >> 1;

    float acc[4][4][4];
#pragma unroll
    for (int i = 0; i < 4; i++)
#pragma unroll
        for (int j = 0; j < 4; j++)
#pragma unroll
            for (int q = 0; q < 4; q++) acc[i][j][q] = 0.f;

#define ISSUE(c, stg)                                                          \
    do {                                                                       \
        uint32_t dS = sbase + (stg)*STAGE_BYTES;                               \
        int k0 = (c) * 32;                                                     \
        cp_async16(dS + S_A + aDst0, Arow + k0);                               \
        cp_async16(dS + S_A + aDst1, Arow + k0 + 8);                           \
        const __half* bp = Bptr + (size_t)k0 * HID;                            \
        cp_async16(dS + S_B + bDst0, bp);                                      \
        cp_async16(dS + S_B + bDst1, bp + 8);                                  \
        CP_COMMIT();                                                           \
    } while (0)

#define COMPUTE(stg)                                                           \
    do {                                                                       \
        uint32_t aB = sbase + (stg)*STAGE_BYTES + S_A;                         \
        uint32_t bB = sbase + (stg)*STAGE_BYTES + S_B;                         \
        _Pragma("unroll")                                                      \
        for (int ks = 0; ks < 2; ks++) {                                       \
            uint32_t ah[4][4];                                                 \
            _Pragma("unroll")                                                  \
            for (int i = 0; i < 4; i++) {                                      \
                int r = wm * 64 + i * 16 + (lane & 15);                        \
                int cb = ks*32 + ((lane >> 4) << 4);                           \
                ldsm4(ah[i][0], ah[i][1], ah[i][2], ah[i][3],                  \
                      aB + (uint32_t)SWZA(r, cb));                             \
            }                                                                  \
            uint32_t bh[4][2];                                                 \
            _Pragma("unroll")                                                  \
            for (int jp = 0; jp < 2; jp++) {                                   \
                int r = ks * 16 + (lane & 15);                                 \
                int cb = wn * 64 + jp * 32 + ((lane >> 4) << 4);               \
                uint32_t ad = (uint32_t)SWZB(r, cb);                           \
                uint32_t r0,r1,r2,r3;                                          \
                ldsm4t(r0, r1, r2, r3, bB + ad);                               \
                bh[jp*2][0]=r0; bh[jp*2][1]=r1; bh[jp*2+1][0]=r2; bh[jp*2+1][1]=r3; \
            }                                                                  \
            _Pragma("unroll")                                                  \
            for (int i = 0; i < 4; i++)                                        \
                _Pragma("unroll")                                              \
                for (int j = 0; j < 4; j++)                                    \
                    mma16816(acc[i][j], ah[i], bh[j][0], bh[j][1]);            \
        }                                                                      \
    } while (0)

#define NC (DIM/32)
    // Prologue: fill 3 stages
    ISSUE(0, 0);
    ISSUE(1, 1);
    ISSUE(2, 2);

#pragma unroll 1
    for (int c = 0; c < NC; c++) {
        int stg = c & 3;
        CP_WAIT(2);            // stage c complete (c+1, c+2 may be in flight)
        __syncthreads();       // all threads see stage c; all past compute(c-1)
        COMPUTE(stg);
        if (c + 3 < NC) {
            ISSUE(c + 3, (c + 3) & 3);
        } else {
            CP_COMMIT();       // keep group count in sync for CP_WAIT
        }
    }
#undef NC

    // Epilogue (fp16 outputs for both passes)
    int colb = wn * 32 + (lane & 3) * 2;
    float2 bz[4];
#pragma unroll
    for (int j = 0; j < 4; j++)
        bz[j] = *(const float2*)(bias + e * HID + n0 + colb + j * 8);

#pragma unroll
    for (int i = 0; i < 4; i++) {
#pragma unroll
        for (int rh = 0; rh < 2; rh++) {
            int row = wm * 64 + i * 16 + rh * 8 + (lane >> 2);
            int aid = rowid[row];
            if (aid < 0) continue;
#pragma unroll
            for (int j = 0; j < 4; j++) {
                float ox = acc[i][j][rh*2+0] + bz[j].x;
                float oy = acc[i][j][rh*2+1] + bz[j].y;
                if (pass1) {
                    ox = fmaxf(ox, 0.f); oy = fmaxf(oy, 0.f);
                    __half2 h = __float22half2_rn(make_float2(ox, oy));
                    *(__half2*)(g_h16 + (size_t)aid * HID + n0 + colb + j * 8) = h;
                } else {
                    __half2 h = __float22half2_rn(make_float2(ox, oy));
                    *(__half2*)(g_o16 + (size_t)aid * DIM + n0 + colb + j * 8) = h;
                }
            }
        }
    }
#undef ISSUE
#undef COMPUTE
}

__device__ float block_reduce_256(float v, volatile float* red) {
    int t = threadIdx.x;
    red[t] = v; __syncthreads();
    if (t < 128) red[t] += red[t + 128]; __syncthreads();
    if (t <  64) red[t] += red[t +  64]; __syncthreads();
    if (t <  32) {
        red[t] += red[t + 32]; __syncwarp();
        red[t] += red[t + 16]; __syncwarp();
        red[t] += red[t +  8]; __syncwarp();
        red[t] += red[t +  4]; __syncwarp();
        red[t] += red[t +  2]; __syncwarp();
        red[t] += red[t +  1]; __syncwarp();
    }
    __syncthreads();
    float r = red[0];
    __syncthreads();
    return r;
}

// Combine (fp16 g_o16), layernorm, head, MSE partials + aux loss.
// d_out[641] must be zeroed before this kernel (memset node).
__global__ void finalize_kernel(const float* __restrict__ ln_w,
                                const float* __restrict__ ln_b,
                                const float* __restrict__ W_los,
                                const float* __restrict__ b_los,
                                const float* __restrict__ true_y,
                                float* __restrict__ d_out) {
    __shared__ float red[256];
    int b = blockIdx.x, t = threadIdx.x;
    float v[2][2];
#pragma unroll
    for (int i = 0; i < 2; i++) {
        int d0 = i * 512 + t * 2;
        float a0 = 0.f, a1 = 0.f;
        for (int m = 0; m < NM; m++) {
            int n = (b << 4) + m;
#pragma unroll
            for (int k = 0; k < 4; k++) {
                int a = (n << 2) + k;
                __half2 h = *(const __half2*)(g_o16 + (size_t)a * DIM + d0);
                float2 f = __half22float2(h);
                float g = g_tk_gate[a];
                a0 = fmaf(g, f.x, a0);
                a1 = fmaf(g, f.y, a1);
            }
        }
        v[i][0] = a0; v[i][1] = a1;
    }
    float s = 0.f, ss = 0.f;
#pragma unroll
    for (int i = 0; i < 2; i++)
#pragma unroll
        for (int p = 0; p < 2; p++) { s += v[i][p]; ss = fmaf(v[i][p], v[i][p], ss); }
    float sum   = block_reduce_256(s,  red);
    float sumsq = block_reduce_256(ss, red);
    float mu   = sum * (1.f / 1024.f);
    float var  = sumsq * (1.f / 1024.f) - mu * mu;
    float rstd = 1.f / sqrtf(var + 1e-5f);

    float sc[10];
#pragma unroll
    for (int o = 0; o < 10; o++) sc[o] = 0.f;
#pragma unroll
    for (int i = 0; i < 2; i++)
#pragma unroll
        for (int p = 0; p < 2; p++) {
            int d = i * 512 + t * 2 + p;
            float f = (v[i][p] - mu) * rstd * ln_w[d] + ln_b[d];
            const float* wl = W_los + (size_t)d * NOUT;
#pragma unroll
            for (int o = 0; o < 10; o++) sc[o] = fmaf(f, wl[o], sc[o]);
        }
    float mse = 0.f;
    for (int o = 0; o < 10; o++) {
        float r = block_reduce_256(sc[o], red);
        if (t == 0) {
            float sval = r + b_los[o];
            d_out[b * NOUT + o] = sval;
            float dd = sval - true_y[b * NOUT + o];
            mse = fmaf(dd, dd, mse);
        }
    }
    if (t == 0) {
        atomicAdd(&d_out[641], mse * (1.f / 640.f));
        if (b == 0) {
            float m1 = 0.f, m2 = 0.f;
            for (int e = 0; e < 16; e++) { m1 += g_impld[e]; m2 += g_impld[16 + e]; }
            m1 *= (1.f/16.f); m2 *= (1.f/16.f);
            float v1 = 0.f, v2 = 0.f;
            for (int e = 0; e < 16; e++) {
                float a = g_impld[e] - m1, bb = g_impld[16 + e] - m2;
                v1 += a * a; v2 += bb * bb;
            }
            v1 *= (1.f/15.f); v2 *= (1.f/15.f);
            float cv1 = v1 / (m1*m1 + 1e-10f);
            float cv2 = v2 / (m2*m2 + 1e-10f);
            d_out[640] = (cv1 + cv2) * 0.01f;
        }
    }
}

extern "C" void kernel_launch(void* const* d_in, const int* in_sizes, int n_in,
                              void* d_out, int out_size) {
    const float* x      = (const float*)d_in[0];
    const float* wg     = (const float*)d_in[1];
    const float* W1     = (const float*)d_in[2];
    const float* b1     = (const float*)d_in[3];
    const float* W2     = (const float*)d_in[4];
    const float* b2     = (const float*)d_in[5];
    const float* ln_w   = (const float*)d_in[6];
    const float* ln_b   = (const float*)d_in[7];
    const float* W_los  = (const float*)d_in[8];
    const float* b_los  = (const float*)d_in[9];
    const float* true_y = (const float*)d_in[10];
    float* out = (float*)d_out;

    static int inited = 0;
    static void* cnt_addr = nullptr;
    static void* impld_addr = nullptr;
    if (!inited) {
        cudaFuncSetAttribute(expert_gemm_mma,
                             cudaFuncAttributeMaxDynamicSharedMemorySize, SMEM_TOTAL);
        cudaGetSymbolAddress(&cnt_addr, g_cnt);
        cudaGetSymbolAddress(&impld_addr, g_impld);
        inited = 1;
    }

    __half *w1h = nullptr, *w2h = nullptr;
    cudaGetSymbolAddress((void**)&w1h, g_w1h);
    cudaGetSymbolAddress((void**)&w2h, g_w2h);

    cudaMemsetAsync(cnt_addr, 0, NE * sizeof(int), 0);
    cudaMemsetAsync(impld_addr, 0, 2 * NE * sizeof(float), 0);
    cudaMemsetAsync(out + 641, 0, sizeof(float), 0);
    gate_kernel<<<128, 256>>>(x, wg);
    convert_w_kernel<<<16384, 256>>>(W1, w1h, W2, w2h);
    expert_gemm_mma<<<dim3(8, 8, 16), 256, SMEM_TOTAL>>>(w1h, b1, 1);
    expert_gemm_mma<<<dim3(8, 8, 16), 256, SMEM_TOTAL>>>(w2h, b2, 0);
    finalize_kernel<<<64, 256>>>(ln_w, ln_b, W_los, b_los, true_y, out);
}

// round 14
// speedup vs baseline: 1.1902x; 1.0536x over previous
#include <cuda_runtime.h>
#include <cuda_fp16.h>
#include <math.h>
#include <stdint.h>

// Problem constants
#define NTOK 1024
#define DIM  1024
#define HID  1024
#define NE   16
#define NK   4
#define NA   (NTOK*NK)
#define NOUT 10
#define NB   64
#define NM   16

// Scratch (device globals: allocation-free)
__device__ __align__(16) __half g_x16[(size_t)NTOK*DIM];   // 2 MB
__device__ __align__(16) __half g_h16[(size_t)NA*HID];     // 8 MB
__device__ __align__(16) __half g_o16[(size_t)NA*DIM];     // 8 MB
__device__ __align__(16) __half g_w1h[(size_t)NE*DIM*HID]; // 32 MB
__device__ __align__(16) __half g_w2h[(size_t)NE*HID*DIM]; // 32 MB
__device__ int   g_tk_idx[NA];
__device__ float g_tk_gate[NA];
__device__ int   g_cnt[NE];
__device__ int   g_list[NE*NTOK];
__device__ float g_impld[2*NE];   // [0:16) importance, [16:32) load

__device__ __forceinline__ uint32_t smem_u32(const void* p) {
    uint32_t a;
    asm("{ .reg .u64 t; cvta.to.shared.u64 t, %1; cvt.u32.u64 %0, t; }" : "=r"(a) : "l"(p));
    return a;
}
__device__ __forceinline__ void ldsm4(uint32_t& r0, uint32_t& r1, uint32_t& r2, uint32_t& r3, uint32_t a) {
    asm volatile("ldmatrix.sync.aligned.m8n8.x4.shared.b16 {%0,%1,%2,%3}, [%4];"
                 : "=r"(r0), "=r"(r1), "=r"(r2), "=r"(r3) : "r"(a));
}
__device__ __forceinline__ void ldsm4t(uint32_t& r0, uint32_t& r1, uint32_t& r2, uint32_t& r3, uint32_t a) {
    asm volatile("ldmatrix.sync.aligned.m8n8.x4.trans.shared.b16 {%0,%1,%2,%3}, [%4];"
                 : "=r"(r0), "=r"(r1), "=r"(r2), "=r"(r3) : "r"(a));
}
__device__ __forceinline__ void mma16816(float* c, const uint32_t* a, uint32_t b0, uint32_t b1) {
    asm volatile("mma.sync.aligned.m16n8k16.row.col.f32.f16.f16.f32 "
                 "{%0,%1,%2,%3}, {%4,%5,%6,%7}, {%8,%9}, {%0,%1,%2,%3};"
                 : "+f"(c[0]), "+f"(c[1]), "+f"(c[2]), "+f"(c[3])
                 : "r"(a[0]), "r"(a[1]), "r"(a[2]), "r"(a[3]), "r"(b0), "r"(b1));
}
__device__ __forceinline__ void cp_async16(uint32_t dst, const void* src) {
    asm volatile("cp.async.cg.shared.global [%0], [%1], 16;" :: "r"(dst), "l"(src));
}
#define CP_COMMIT() asm volatile("cp.async.commit_group;" ::: "memory")
#define CP_WAIT(n)  asm volatile("cp.async.wait_group %0;" :: "n"(n) : "memory")

// Swizzles (conflict-free ldsm phases)
#define SWZA(row, cb)   ((row)*64  + ((cb) ^ ((((row)>>1)&3)<<4)))
#define SWZB(row, cb)   ((row)*256 + ((cb) ^ (((row)&7)<<4)))

// stage layout: A 8KB (128 rows x 64B) | B 8KB (32 k-rows x 256B), KC=32
#define S_A   0
#define S_B   (128*64)
#define STAGE_BYTES (128*64 + 32*256)     // 16KB
#define NSTAGE 6
#define SMEM_TOTAL  (NSTAGE*STAGE_BYTES)  // 96KB -> 2 CTAs/SM (192KB)

// Both W1 and W2 fp32 -> fp16 in ONE launch (grid 16384; upper half = W2)
__global__ void convert_w_kernel(const float* __restrict__ W1, __half* __restrict__ W1h,
                                 const float* __restrict__ W2, __half* __restrict__ W2h) {
    int blk = blockIdx.x;
    const float* W  = (blk < 8192) ? W1  : W2;
    __half*      Wh = (blk < 8192) ? W1h : W2h;
    if (blk >= 8192) blk -= 8192;
    size_t i = ((size_t)blk * 256 + threadIdx.x) * 8;
    float4 a = *(const float4*)(W + i);
    float4 b = *(const float4*)(W + i + 4);
    __half2 h[4];
    h[0] = __float22half2_rn(make_float2(a.x, a.y));
    h[1] = __float22half2_rn(make_float2(a.z, a.w));
    h[2] = __float22half2_rn(make_float2(b.x, b.y));
    h[3] = __float22half2_rn(make_float2(b.z, b.w));
    *(uint4*)(Wh + i) = *(uint4*)h;
}

// Warp-per-token gate: logits, top-4, softmax, routing, aux-loss sums; x -> fp16.
// 128 blocks x 256 threads = 1024 warps = 1024 tokens.
__global__ void gate_kernel(const float* __restrict__ x, const float* __restrict__ wg) {
    int w = threadIdx.x >> 5, lane = threadIdx.x & 31;
    int n = blockIdx.x * 8 + w;
    const float* xr = x + (size_t)n * DIM;
    __half* xo = g_x16 + (size_t)n * DIM;

    float acc[16];
#pragma unroll
    for (int e = 0; e < 16; e++) acc[e] = 0.f;

#pragma unroll
    for (int i = 0; i < 8; i++) {
        int d0 = i * 128 + lane * 4;
        float4 xv = *(const float4*)(xr + d0);
        __half2 h0 = __float22half2_rn(make_float2(xv.x, xv.y));
        __half2 h1 = __float22half2_rn(make_float2(xv.z, xv.w));
        uint2 hp; hp.x = *(uint32_t*)&h0; hp.y = *(uint32_t*)&h1;
        *(uint2*)(xo + d0) = hp;
        float xs[4] = {xv.x, xv.y, xv.z, xv.w};
#pragma unroll
        for (int j = 0; j < 4; j++) {
            const float4* wr = (const float4*)(wg + (size_t)(d0 + j) * 16);
#pragma unroll
            for (int q = 0; q < 4; q++) {
                float4 ww = wr[q];
                acc[q*4+0] = fmaf(xs[j], ww.x, acc[q*4+0]);
                acc[q*4+1] = fmaf(xs[j], ww.y, acc[q*4+1]);
                acc[q*4+2] = fmaf(xs[j], ww.z, acc[q*4+2]);
                acc[q*4+3] = fmaf(xs[j], ww.w, acc[q*4+3]);
            }
        }
    }
#pragma unroll
    for (int e = 0; e < 16; e++)
#pragma unroll
        for (int off = 16; off; off >>= 1)
            acc[e] += __shfl_xor_sync(0xffffffffu, acc[e], off);

    if (lane == 0) {
        int   idx[4];
        float val[4];
#pragma unroll
        for (int k = 0; k < 4; k++) {       // strict > : lowest index wins ties
            float best = -INFINITY; int bi = 0;
            for (int e = 0; e < 16; e++) if (acc[e] > best) { best = acc[e]; bi = e; }
            idx[k] = bi; val[k] = best; acc[bi] = -INFINITY;
        }
        float mx = val[0], s = 0.f, ex[4];
#pragma unroll
        for (int k = 0; k < 4; k++) { ex[k] = expf(val[k] - mx); s += ex[k]; }
        float inv = 1.f / s;
#pragma unroll
        for (int k = 0; k < 4; k++) {
            float g = ex[k] * inv;
            int a = n * 4 + k;
            g_tk_idx[a]  = idx[k];
            g_tk_gate[a] = g;
            int slot = atomicAdd(&g_cnt[idx[k]], 1);
            g_list[idx[k] * NTOK + slot] = a;   // list order irrelevant downstream
            atomicAdd(&g_impld[idx[k]], g);       // importance
            atomicAdd(&g_impld[16 + idx[k]], 1.f);// load
        }
    }
}

// Single fp16 expert GEMM, all-cp.async, 6-stage pipeline.
// CTA 128(M) x 128(N), KC=32, 8 warps = 2(m) x 4(n), warp tile 64x32.
__global__ void __launch_bounds__(256, 2)
expert_gemm_mma(const __half* __restrict__ Wh,
                const float* __restrict__ bias,
                int pass1) {
    int e   = blockIdx.z;
    int cnt = g_cnt[e];
    int m0  = blockIdx.y << 7;
    if (m0 >= cnt) return;
    int n0  = blockIdx.x << 7;

    extern __shared__ __align__(16) uint8_t smem[];
    __shared__ int rowid[128];

    const __half* We = Wh + (size_t)e * DIM * HID;

    int t = threadIdx.x, wid = t >> 5, lane = t & 31;

    if (t < 128) {
        int mi = m0 + t;
        rowid[t] = (mi < cnt) ? g_list[e * NTOK + mi] : -1;
    }
    __syncthreads();

    // A staging: row = t>>1, half = t&1 (16 fp16 = 32B; 2 x cp.async 16B)
    int arow = t >> 1, ahalf = t & 1;
    int aid_s = rowid[arow];
    int asrc = 0;
    if (aid_s >= 0) asrc = pass1 ? (aid_s >> 2) : aid_s;
    const __half* Arow = (pass1 ? g_x16 : g_h16) + (size_t)asrc * DIM + ahalf * 16;
    uint32_t aDst0 = (uint32_t)SWZA(arow, ahalf*32);
    uint32_t aDst1 = (uint32_t)SWZA(arow, ahalf*32 + 16);
    // B staging: krow = t>>3 (32 rows), 8 threads/row, 16 fp16 = 32B each
    int bkr = t >> 3, bseg = t & 7;
    const __half* Bptr = We + (size_t)bkr * HID + n0 + bseg * 16;
    uint32_t bDst0 = (uint32_t)SWZB(bkr, bseg*32);
    uint32_t bDst1 = (uint32_t)SWZB(bkr, bseg*32 + 16);

    uint32_t sbase = smem_u32(smem);
    int wm = wid & 1, wn = wid >> 1;

    float acc[4][4][4];
#pragma unroll
    for (int i = 0; i < 4; i++)
#pragma unroll
        for (int j = 0; j < 4; j++)
#pragma unroll
            for (int q = 0; q < 4; q++) acc[i][j][q] = 0.f;

#define ISSUE(c, stg)                                                          \
    do {                                                                       \
        uint32_t dS = sbase + (stg)*STAGE_BYTES;                               \
        int k0 = (c) * 32;                                                     \
        cp_async16(dS + S_A + aDst0, Arow + k0);                               \
        cp_async16(dS + S_A + aDst1, Arow + k0 + 8);                           \
        const __half* bp = Bptr + (size_t)k0 * HID;                            \
        cp_async16(dS + S_B + bDst0, bp);                                      \
        cp_async16(dS + S_B + bDst1, bp + 8);                                  \
        CP_COMMIT();                                                           \
    } while (0)

#define COMPUTE(stg)                                                           \
    do {                                                                       \
        uint32_t aB = sbase + (stg)*STAGE_BYTES + S_A;                         \
        uint32_t bB = sbase + (stg)*STAGE_BYTES + S_B;                         \
        _Pragma("unroll")                                                      \
        for (int ks = 0; ks < 2; ks++) {                                       \
            uint32_t ah[4][4];                                                 \
            _Pragma("unroll")                                                  \
            for (int i = 0; i < 4; i++) {                                      \
                int r = wm * 64 + i * 16 + (lane & 15);                        \
                int cb = ks*32 + ((lane >> 4) << 4);                           \
                ldsm4(ah[i][0], ah[i][1], ah[i][2], ah[i][3],                  \
                      aB + (uint32_t)SWZA(r, cb));                             \
            }                                                                  \
            uint32_t bh[4][2];                                                 \
            _Pragma("unroll")                                                  \
            for (int jp = 0; jp < 2; jp++) {                                   \
                int r = ks * 16 + (lane & 15);                                 \
                int cb = wn * 64 + jp * 32 + ((lane >> 4) << 4);               \
                uint32_t ad = (uint32_t)SWZB(r, cb);                           \
                uint32_t r0,r1,r2,r3;                                          \
                ldsm4t(r0, r1, r2, r3, bB + ad);                               \
                bh[jp*2][0]=r0; bh[jp*2][1]=r1; bh[jp*2+1][0]=r2; bh[jp*2+1][1]=r3; \
            }                                                                  \
            _Pragma("unroll")                                                  \
            for (int i = 0; i < 4; i++)                                        \
                _Pragma("unroll")                                              \
                for (int j = 0; j < 4; j++)                                    \
                    mma16816(acc[i][j], ah[i], bh[j][0], bh[j][1]);            \
        }                                                                      \
    } while (0)

#define NC (DIM/32)
    // Prologue: fill 5 stages
    ISSUE(0, 0);
    ISSUE(1, 1);
    ISSUE(2, 2);
    ISSUE(3, 3);
    ISSUE(4, 4);

#pragma unroll 1
    for (int c = 0; c < NC; c++) {
        int stg = c % NSTAGE;
        CP_WAIT(4);            // stage c complete (c+1..c+4 may be in flight)
        __syncthreads();       // all threads see stage c; all past compute(c-1)
        COMPUTE(stg);
        if (c + 5 < NC) {
            ISSUE(c + 5, (c + 5) % NSTAGE);
        } else {
            CP_COMMIT();       // keep group count in sync for CP_WAIT
        }
    }
#undef NC

    // Epilogue (fp16 outputs for both passes)
    int colb = wn * 32 + (lane & 3) * 2;
    float2 bz[4];
#pragma unroll
    for (int j = 0; j < 4; j++)
        bz[j] = *(const float2*)(bias + e * HID + n0 + colb + j * 8);

#pragma unroll
    for (int i = 0; i < 4; i++) {
#pragma unroll
        for (int rh = 0; rh < 2; rh++) {
            int row = wm * 64 + i * 16 + rh * 8 + (lane >> 2);
            int aid = rowid[row];
            if (aid < 0) continue;
#pragma unroll
            for (int j = 0; j < 4; j++) {
                float ox = acc[i][j][rh*2+0] + bz[j].x;
                float oy = acc[i][j][rh*2+1] + bz[j].y;
                if (pass1) {
                    ox = fmaxf(ox, 0.f); oy = fmaxf(oy, 0.f);
                    __half2 h = __float22half2_rn(make_float2(ox, oy));
                    *(__half2*)(g_h16 + (size_t)aid * HID + n0 + colb + j * 8) = h;
                } else {
                    __half2 h = __float22half2_rn(make_float2(ox, oy));
                    *(__half2*)(g_o16 + (size_t)aid * DIM + n0 + colb + j * 8) = h;
                }
            }
        }
    }
#undef ISSUE
#undef COMPUTE
}

__device__ float block_reduce_512(float v, volatile float* red) {
    int t = threadIdx.x;
    red[t] = v; __syncthreads();
    if (t < 256) red[t] += red[t + 256]; __syncthreads();
    if (t < 128) red[t] += red[t + 128]; __syncthreads();
    if (t <  64) red[t] += red[t +  64]; __syncthreads();
    if (t <  32) {
        red[t] += red[t + 32]; __syncwarp();
        red[t] += red[t + 16]; __syncwarp();
        red[t] += red[t +  8]; __syncwarp();
        red[t] += red[t +  4]; __syncwarp();
        red[t] += red[t +  2]; __syncwarp();
        red[t] += red[t +  1]; __syncwarp();
    }
    __syncthreads();
    float r = red[0];
    __syncthreads();
    return r;
}

// Combine (fp16 g_o16), layernorm, head, MSE partials + aux loss. 512 threads.
// d_out[641] must be zeroed before this kernel (memset node).
__global__ void finalize_kernel(const float* __restrict__ ln_w,
                                const float* __restrict__ ln_b,
                                const float* __restrict__ W_los,
                                const float* __restrict__ b_los,
                                const float* __restrict__ true_y,
                                float* __restrict__ d_out) {
    __shared__ float red[512];
    __shared__ float gates[64];
    int b = blockIdx.x, t = threadIdx.x;
    if (t < 64) gates[t] = g_tk_gate[(b << 6) + t];   // a = b*64 + (m*4+k), contiguous
    __syncthreads();

    int d0 = t * 2;
    float a0 = 0.f, a1 = 0.f;
#pragma unroll 4
    for (int idx = 0; idx < 64; idx++) {
        int a = (b << 6) + idx;
        __half2 h = *(const __half2*)(g_o16 + (size_t)a * DIM + d0);
        float2 f = __half22float2(h);
        float g = gates[idx];
        a0 = fmaf(g, f.x, a0);
        a1 = fmaf(g, f.y, a1);
    }
    float s = a0 + a1;
    float ss = fmaf(a0, a0, a1 * a1);
    float sum   = block_reduce_512(s,  red);
    float sumsq = block_reduce_512(ss, red);
    float mu   = sum * (1.f / 1024.f);
    float var  = sumsq * (1.f / 1024.f) - mu * mu;
    float rstd = 1.f / sqrtf(var + 1e-5f);

    float f0 = (a0 - mu) * rstd * ln_w[d0]   + ln_b[d0];
    float f1 = (a1 - mu) * rstd * ln_w[d0+1] + ln_b[d0+1];
    const float* wl0 = W_los + (size_t)d0 * NOUT;
    const float* wl1 = W_los + (size_t)(d0+1) * NOUT;
    float sc[10];
#pragma unroll
    for (int o = 0; o < 10; o++) sc[o] = fmaf(f0, wl0[o], f1 * wl1[o]);

    float mse = 0.f;
    for (int o = 0; o < 10; o++) {
        float r = block_reduce_512(sc[o], red);
        if (t == 0) {
            float sval = r + b_los[o];
            d_out[b * NOUT + o] = sval;
            float dd = sval - true_y[b * NOUT + o];
            mse = fmaf(dd, dd, mse);
        }
    }
    if (t == 0) {
        atomicAdd(&d_out[641], mse * (1.f / 640.f));
        if (b == 0) {
            float m1 = 0.f, m2 = 0.f;
            for (int e = 0; e < 16; e++) { m1 += g_impld[e]; m2 += g_impld[16 + e]; }
            m1 *= (1.f/16.f); m2 *= (1.f/16.f);
            float v1 = 0.f, v2 = 0.f;
            for (int e = 0; e < 16; e++) {
                float a = g_impld[e] - m1, bb = g_impld[16 + e] - m2;
                v1 += a * a; v2 += bb * bb;
            }
            v1 *= (1.f/15.f); v2 *= (1.f/15.f);
            float cv1 = v1 / (m1*m1 + 1e-10f);
            float cv2 = v2 / (m2*m2 + 1e-10f);
            d_out[640] = (cv1 + cv2) * 0.01f;
        }
    }
}

extern "C" void kernel_launch(void* const* d_in, const int* in_sizes, int n_in,
                              void* d_out, int out_size) {
    const float* x      = (const float*)d_in[0];
    const float* wg     = (const float*)d_in[1];
    const float* W1     = (const float*)d_in[2];
    const float* b1     = (const float*)d_in[3];
    const float* W2     = (const float*)d_in[4];
    const float* b2     = (const float*)d_in[5];
    const float* ln_w   = (const float*)d_in[6];
    const float* ln_b   = (const float*)d_in[7];
    const float* W_los  = (const float*)d_in[8];
    const float* b_los  = (const float*)d_in[9];
    const float* true_y = (const float*)d_in[10];
    float* out = (float*)d_out;

    static int inited = 0;
    static void* cnt_addr = nullptr;
    static void* impld_addr = nullptr;
    if (!inited) {
        cudaFuncSetAttribute(expert_gemm_mma,
                             cudaFuncAttributeMaxDynamicSharedMemorySize, SMEM_TOTAL);
        cudaGetSymbolAddress(&cnt_addr, g_cnt);
        cudaGetSymbolAddress(&impld_addr, g_impld);
        inited = 1;
    }

    __half *w1h = nullptr, *w2h = nullptr;
    cudaGetSymbolAddress((void**)&w1h, g_w1h);
    cudaGetSymbolAddress((void**)&w2h, g_w2h);

    cudaMemsetAsync(cnt_addr, 0, NE * sizeof(int), 0);
    cudaMemsetAsync(impld_addr, 0, 2 * NE * sizeof(float), 0);
    cudaMemsetAsync(out + 641, 0, sizeof(float), 0);
    gate_kernel<<<128, 256>>>(x, wg);
    convert_w_kernel<<<16384, 256>>>(W1, w1h, W2, w2h);
    expert_gemm_mma<<<dim3(8, 8, 16), 256, SMEM_TOTAL>>>(w1h, b1, 1);
    expert_gemm_mma<<<dim3(8, 8, 16), 256, SMEM_TOTAL>>>(w2h, b2, 0);
    finalize_kernel<<<64, 512>>>(ln_w, ln_b, W_los, b_los, true_y, out);
}